// round 12
// baseline (speedup 1.0000x reference)
#include <cuda_runtime.h>
#include <cuda_bf16.h>
#include <cstdint>

#define N_NODES 100000
#define N_EDGES 200000
#define D_NODE 128
#define D_EDGE 16
#define N_REL 3

// ───────────────────────── scratch ─────────────────────────
__device__ float g_Y[(size_t)N_NODES * 384];              // x @ [W_rel0|W_rel1|W_rel2], 153.6 MB
__device__ float g_acc[(size_t)N_NODES * D_NODE];         // scattered sum, 51.2 MB (L2-resident)
__device__ float g_E[(size_t)N_REL * N_NODES * D_EDGE];   // 19.2 MB (L2-resident)
// pre-split weights, [chunk][n=128][k=64] bf16:
// c0-1: W_self halves, c2-7: W_rel[r] halves, c8-10: We_rel[r] (k<16, padded)
__device__ __nv_bfloat16 g_Wh[11 * 128 * 64];
__device__ __nv_bfloat16 g_Wl[11 * 128 * 64];

// ─────────────── prep: zero acc+E, split weights (one launch) ───────────────
__global__ void prep_kernel(const float* __restrict__ W_rel,
                            const float* __restrict__ We_rel,
                            const float* __restrict__ W_self) {
    int gtid = blockIdx.x * blockDim.x + threadIdx.x;

    if (gtid < 11 * 128 * 64) {
        int c = gtid / (128 * 64);
        int rem = gtid - c * (128 * 64);
        int n = rem >> 6, j = rem & 63;
        float v = 0.f;
        if (c < 2)       v = W_self[(c * 64 + j) * 128 + n];
        else if (c < 8)  { int r = (c - 2) >> 1, h = (c - 2) & 1;
                           v = W_rel[r * 16384 + (h * 64 + j) * 128 + n]; }
        else             { int r = c - 8; if (j < 16) v = We_rel[r * 2048 + j * 128 + n]; }
        __nv_bfloat16 hb = __float2bfloat16_rn(v);
        g_Wh[gtid] = hb;
        g_Wl[gtid] = __float2bfloat16_rn(v - __bfloat162float(hb));
    }

    const size_t nAcc = (size_t)N_NODES * D_NODE / 4;
    const size_t nE   = (size_t)N_REL * N_NODES * D_EDGE / 4;
    float4 z = make_float4(0.f, 0.f, 0.f, 0.f);
    float4* C4 = reinterpret_cast<float4*>(g_acc);
    float4* E4 = reinterpret_cast<float4*>(g_E);
    size_t stride = (size_t)gridDim.x * blockDim.x;
    for (size_t i = gtid; i < nAcc; i += stride) C4[i] = z;
    for (size_t i = gtid; i < nE;   i += stride) E4[i] = z;
}

// ───────────── scatter: acc[dst] += Y[src, r·128:…], E_r[dst] += edge_attr ────
__global__ void scatter_kernel(const float* __restrict__ edge_attr,
                               const int*   __restrict__ edge_index) {
    int w = (blockIdx.x * blockDim.x + threadIdx.x) >> 5;
    int lane = threadIdx.x & 31;
    if (w >= N_REL * N_EDGES) return;
    int r = w / N_EDGES;
    int e = w - r * N_EDGES;

    int2 se = reinterpret_cast<const int2*>(edge_index)[w];
    int src = se.x, dst = se.y;

    const float4* yr = reinterpret_cast<const float4*>(g_Y + (size_t)src * 384 + r * 128);
    float4 v = yr[lane];
    float* a = g_acc + (size_t)dst * D_NODE + lane * 4;
    asm volatile("red.global.add.v4.f32 [%0], {%1,%2,%3,%4};"
                 :: "l"(a), "f"(v.x), "f"(v.y), "f"(v.z), "f"(v.w) : "memory");

    if (lane < 4) {
        const float4* er = reinterpret_cast<const float4*>(
            edge_attr + ((size_t)r * N_EDGES + e) * D_EDGE);
        float4 u = er[lane];
        float* ep = g_E + ((size_t)r * N_NODES + dst) * D_EDGE + lane * 4;
        asm volatile("red.global.add.v4.f32 [%0], {%1,%2,%3,%4};"
                     :: "l"(ep), "f"(u.x), "f"(u.y), "f"(u.z), "f"(u.w) : "memory");
    }
}

// ───────────────── bf16x3 GEMM machinery (pipelined, proven) ──────────────────
__device__ __forceinline__ uint32_t smem_u32(const void* p) {
    uint32_t a;
    asm("{ .reg .u64 t; cvta.to.shared.u64 t, %1; cvt.u32.u64 %0, t; }" : "=r"(a) : "l"(p));
    return a;
}
__device__ __forceinline__ void ldsm4(uint32_t* r, uint32_t addr) {
    asm volatile("ldmatrix.sync.aligned.m8n8.x4.shared.b16 {%0,%1,%2,%3}, [%4];"
                 : "=r"(r[0]), "=r"(r[1]), "=r"(r[2]), "=r"(r[3]) : "r"(addr));
}
__device__ __forceinline__ void cpa16(uint32_t s, const void* g) {
    asm volatile("cp.async.ca.shared.global [%0], [%1], 16;" :: "r"(s), "l"(g));
}
__device__ __forceinline__ void mma16816(float* c, const uint32_t* a,
                                         uint32_t b0, uint32_t b1) {
    asm volatile(
        "mma.sync.aligned.m16n8k16.row.col.f32.bf16.bf16.f32 "
        "{%0,%1,%2,%3}, {%4,%5,%6,%7}, {%8,%9}, {%0,%1,%2,%3};"
        : "+f"(c[0]), "+f"(c[1]), "+f"(c[2]), "+f"(c[3])
        : "r"(a[0]), "r"(a[1]), "r"(a[2]), "r"(a[3]), "r"(b0), "r"(b1));
}
__device__ __forceinline__ void split8(const float* f, uint4& hi, uint4& lo) {
    uint32_t h[8], l[8];
#pragma unroll
    for (int j = 0; j < 8; ++j) {
        __nv_bfloat16 hb = __float2bfloat16_rn(f[j]);
        float r = f[j] - __bfloat162float(hb);
        __nv_bfloat16 lb = __float2bfloat16_rn(r);
        h[j] = (uint32_t)__bfloat16_as_ushort(hb);
        l[j] = (uint32_t)__bfloat16_as_ushort(lb);
    }
    hi.x = h[0] | (h[1] << 16); hi.y = h[2] | (h[3] << 16);
    hi.z = h[4] | (h[5] << 16); hi.w = h[6] | (h[7] << 16);
    lo.x = l[0] | (l[1] << 16); lo.y = l[2] | (l[3] << 16);
    lo.z = l[4] | (l[5] << 16); lo.w = l[6] | (l[7] << 16);
}

#define KPAD 72
static constexpr int TILE_B   = 128 * KPAD * 2;
static constexpr int OFF_AH   = 0;
static constexpr int OFF_AL   = OFF_AH + TILE_B;
static constexpr int OFF_B0   = 2 * TILE_B;
static constexpr int B_STRIDE = 2 * TILE_B;
static constexpr int SMEM_TOTAL = OFF_B0 + 2 * B_STRIDE; // 110592 B

struct Chunk { const float* a; int ld, kb, kw, wc; };

// NC = number of chunks; chunks provided by caller lambda-free via array
template <int NC, bool FINAL>
__device__ __forceinline__ void gemm_body(const Chunk* chunks, int m0,
                                          const float* bias, float* out_ptr,
                                          int out_ld) {
    extern __shared__ char smem[];
    __nv_bfloat16* sAH = reinterpret_cast<__nv_bfloat16*>(smem + OFF_AH);
    __nv_bfloat16* sAL = reinterpret_cast<__nv_bfloat16*>(smem + OFF_AL);
    uint32_t sbase = smem_u32(smem);

    int t = threadIdx.x;
    int wid = t >> 5, lane = t & 31;
    int wm = wid & 3, wn = wid >> 2;

    int arow = (lane & 7) + ((lane & 8) ? 8 : 0);
    int acolb = ((lane & 16) ? 8 : 0) * 2;
    uint32_t aBaseH = sbase + OFF_AH + (uint32_t)(wm * 32 + arow) * (KPAD * 2) + acolb;
    uint32_t aBaseL = aBaseH + TILE_B;
    int brow = (lane & 7) + ((lane & 16) ? 8 : 0);
    int bcolb = ((lane & 8) ? 8 : 0) * 2;
    uint32_t bRowOff = (uint32_t)(wn * 64 + brow) * (KPAD * 2) + bcolb;

    int aRow = t >> 1, aHalf = t & 1;
    float4 ar[8];

    auto load_a = [&](int c) {
        const Chunk& d = chunks[c];
        int gr = m0 + aRow;
        const float* ap = d.a + (size_t)gr * d.ld + d.kb + aHalf * 32;
#pragma unroll
        for (int q = 0; q < 8; ++q) {
            int col = aHalf * 32 + q * 4;
            if (gr < N_NODES && col < d.kw)
                ar[q] = *reinterpret_cast<const float4*>(ap + q * 4);
            else
                ar[q] = make_float4(0.f, 0.f, 0.f, 0.f);
        }
    };
    auto store_a = [&]() {
#pragma unroll
        for (int g = 0; g < 4; ++g) {
            float f[8];
            f[0]=ar[g*2].x; f[1]=ar[g*2].y; f[2]=ar[g*2].z; f[3]=ar[g*2].w;
            f[4]=ar[g*2+1].x; f[5]=ar[g*2+1].y; f[6]=ar[g*2+1].z; f[7]=ar[g*2+1].w;
            uint4 hi, lo; split8(f, hi, lo);
            int col = aHalf * 32 + g * 8;
            *reinterpret_cast<uint4*>(sAH + aRow * KPAD + col) = hi;
            *reinterpret_cast<uint4*>(sAL + aRow * KPAD + col) = lo;
        }
    };
    auto issue_b = [&](int c) {
        const Chunk& d = chunks[c];
        int nseg = d.kw >> 3;
        uint32_t bb = sbase + OFF_B0 + (uint32_t)(c & 1) * B_STRIDE;
        const __nv_bfloat16* gh = g_Wh + d.wc * 8192;
        const __nv_bfloat16* gl = g_Wl + d.wc * 8192;
        for (int i = t; i < 128 * nseg; i += 256) {
            int n = i / nseg, s = i - n * nseg;
            uint32_t dst = bb + (uint32_t)n * (KPAD * 2) + s * 16;
            cpa16(dst, gh + n * 64 + s * 8);
            cpa16(dst + TILE_B, gl + n * 64 + s * 8);
        }
    };

    float acc[2][8][4];
#pragma unroll
    for (int i = 0; i < 2; ++i)
#pragma unroll
        for (int j = 0; j < 8; ++j)
#pragma unroll
            for (int q = 0; q < 4; ++q) acc[i][j][q] = 0.f;

    load_a(0);
    issue_b(0);
    asm volatile("cp.async.commit_group;" ::: "memory");
    store_a();
    asm volatile("cp.async.wait_group 0;" ::: "memory");
    __syncthreads();

    for (int c = 0; c < NC; ++c) {
        int nxt = c + 1;
        if (nxt < NC) { load_a(nxt); issue_b(nxt); }
        asm volatile("cp.async.commit_group;" ::: "memory");

        uint32_t bb = sbase + OFF_B0 + (uint32_t)(c & 1) * B_STRIDE;
        uint32_t bBaseH = bb + bRowOff;
        uint32_t bBaseL = bBaseH + TILE_B;
        int nk = chunks[c].kw >> 4;
        for (int ks = 0; ks < nk; ++ks) {
            uint32_t k0b = (uint32_t)ks * 32;
            uint32_t ah[2][4], bh[4][4];
            ldsm4(ah[0], aBaseH + k0b);
            ldsm4(ah[1], aBaseH + 16 * KPAD * 2 + k0b);
#pragma unroll
            for (int p = 0; p < 4; ++p) ldsm4(bh[p], bBaseH + p * 16 * KPAD * 2 + k0b);
#pragma unroll
            for (int mt = 0; mt < 2; ++mt)
#pragma unroll
                for (int nt = 0; nt < 8; ++nt)
                    mma16816(acc[mt][nt], ah[mt],
                             bh[nt >> 1][(nt & 1) * 2], bh[nt >> 1][(nt & 1) * 2 + 1]);

            uint32_t al[2][4];
            ldsm4(al[0], aBaseL + k0b);
            ldsm4(al[1], aBaseL + 16 * KPAD * 2 + k0b);
#pragma unroll
            for (int mt = 0; mt < 2; ++mt)
#pragma unroll
                for (int nt = 0; nt < 8; ++nt)
                    mma16816(acc[mt][nt], al[mt],
                             bh[nt >> 1][(nt & 1) * 2], bh[nt >> 1][(nt & 1) * 2 + 1]);

            uint32_t bl[4][4];
#pragma unroll
            for (int p = 0; p < 4; ++p) ldsm4(bl[p], bBaseL + p * 16 * KPAD * 2 + k0b);
#pragma unroll
            for (int mt = 0; mt < 2; ++mt)
#pragma unroll
                for (int nt = 0; nt < 8; ++nt)
                    mma16816(acc[mt][nt], ah[mt],
                             bl[nt >> 1][(nt & 1) * 2], bl[nt >> 1][(nt & 1) * 2 + 1]);
        }
        __syncthreads();
        if (nxt < NC) {
            asm volatile("cp.async.wait_group 0;" ::: "memory");
            store_a();
            __syncthreads();
        }
    }

    // epilogue
    int lr = lane >> 2, lc = lane & 3;
#pragma unroll
    for (int mt = 0; mt < 2; ++mt) {
        int r0 = m0 + wm * 32 + mt * 16 + lr;
        int r1 = r0 + 8;
#pragma unroll
        for (int nt = 0; nt < 8; ++nt) {
            int col = wn * 64 + nt * 8 + lc * 2;
            if (FINAL) {
                float b0 = bias[col], b1 = bias[col + 1];
                if (r0 < N_NODES) {
                    float2 pa = *reinterpret_cast<const float2*>(g_acc + (size_t)r0 * 128 + col);
                    float2 v;
                    v.x = fmaxf(acc[mt][nt][0] + pa.x + b0, 0.f);
                    v.y = fmaxf(acc[mt][nt][1] + pa.y + b1, 0.f);
                    *reinterpret_cast<float2*>(out_ptr + (size_t)r0 * out_ld + col) = v;
                }
                if (r1 < N_NODES) {
                    float2 pa = *reinterpret_cast<const float2*>(g_acc + (size_t)r1 * 128 + col);
                    float2 v;
                    v.x = fmaxf(acc[mt][nt][2] + pa.x + b0, 0.f);
                    v.y = fmaxf(acc[mt][nt][3] + pa.y + b1, 0.f);
                    *reinterpret_cast<float2*>(out_ptr + (size_t)r1 * out_ld + col) = v;
                }
            } else {
                if (r0 < N_NODES)
                    *reinterpret_cast<float2*>(out_ptr + (size_t)r0 * out_ld + col) =
                        make_float2(acc[mt][nt][0], acc[mt][nt][1]);
                if (r1 < N_NODES)
                    *reinterpret_cast<float2*>(out_ptr + (size_t)r1 * out_ld + col) =
                        make_float2(acc[mt][nt][2], acc[mt][nt][3]);
            }
        }
    }
}

// Y[:, r·128:(r+1)·128] = x @ W_rel[r]   (grid.y = r)
__global__ __launch_bounds__(256, 2) void gemm_y_kernel(const float* __restrict__ x) {
    int m0 = blockIdx.x * 128;
    int r = blockIdx.y;
    Chunk chunks[2];
    chunks[0] = {x, 128, 0,  64, 2 + 2 * r};
    chunks[1] = {x, 128, 64, 64, 3 + 2 * r};
    gemm_body<2, false>(chunks, m0, nullptr, g_Y + r * 128, 384);
}

// out = relu( x@W_self + Σ_r E_r@We_r + acc + b )
__global__ __launch_bounds__(256, 2) void gemm_out_kernel(
    const float* __restrict__ x,
    const float* __restrict__ bias,
    float* __restrict__ out) {
    int m0 = blockIdx.x * 128;
    Chunk chunks[5];
    chunks[0] = {x, 128, 0,  64, 0};
    chunks[1] = {x, 128, 64, 64, 1};
    chunks[2] = {g_E + (size_t)0 * N_NODES * 16, 16, 0, 16, 8};
    chunks[3] = {g_E + (size_t)1 * N_NODES * 16, 16, 0, 16, 9};
    chunks[4] = {g_E + (size_t)2 * N_NODES * 16, 16, 0, 16, 10};
    gemm_body<5, true>(chunks, m0, bias, out, 128);
}

// ───────────────────────── launch ─────────────────────────
extern "C" void kernel_launch(void* const* d_in, const int* in_sizes, int n_in,
                              void* d_out, int out_size) {
    const float* x          = (const float*)d_in[0];
    const float* edge_attr  = (const float*)d_in[1];
    const float* W_rel      = (const float*)d_in[2];
    const float* We_rel     = (const float*)d_in[3];
    const float* W_self     = (const float*)d_in[4];
    const float* b          = (const float*)d_in[5];
    const int*   edge_index = (const int*)d_in[6];
    float* out = (float*)d_out;

    static bool attr_set = false;
    if (!attr_set) {
        cudaFuncSetAttribute(gemm_y_kernel,
                             cudaFuncAttributeMaxDynamicSharedMemorySize, SMEM_TOTAL);
        cudaFuncSetAttribute(gemm_out_kernel,
                             cudaFuncAttributeMaxDynamicSharedMemorySize, SMEM_TOTAL);
        attr_set = true;
    }

    prep_kernel<<<2048, 256>>>(W_rel, We_rel, W_self);

    int gblocks = (N_NODES + 127) / 128;  // 782
    gemm_y_kernel<<<dim3(gblocks, 3), 256, SMEM_TOTAL>>>(x);

    int n_warps = N_REL * N_EDGES;
    int blocks = (n_warps * 32 + 255) / 256;
    scatter_kernel<<<blocks, 256>>>(edge_attr, edge_index);

    gemm_out_kernel<<<gblocks, 256, SMEM_TOTAL>>>(x, b, out);
}

// round 13
// speedup vs baseline: 1.1779x; 1.1779x over previous
#include <cuda_runtime.h>
#include <cuda_bf16.h>
#include <cstdint>

#define N_NODES 100000
#define N_EDGES 200000
#define D_NODE 128
#define D_EDGE 16
#define N_REL 3

// ───────────────────────── scratch ─────────────────────────
__device__ float g_A[(size_t)N_REL * N_NODES * D_NODE];   // 153.6 MB
__device__ float g_E2[(size_t)N_NODES * 64];              // packed E: [node][r*16..], 25.6 MB
// pre-split weights, 9 chunks × [n=128][k=64] bf16
__device__ __nv_bfloat16 g_Wh[9 * 128 * 64];
__device__ __nv_bfloat16 g_Wl[9 * 128 * 64];

// ─────────────── prep: zero scratch + split weights ───────────────
__global__ void prep_kernel(const float* __restrict__ W_rel,
                            const float* __restrict__ We_rel,
                            const float* __restrict__ W_self) {
    int gtid = blockIdx.x * blockDim.x + threadIdx.x;

    if (gtid < 9 * 128 * 64) {
        int c = gtid / (128 * 64);
        int rem = gtid - c * (128 * 64);
        int n = rem >> 6, j = rem & 63;
        float v = 0.f;
        if (c < 2)       v = W_self[(c * 64 + j) * 128 + n];
        else if (c < 8)  { int r = (c - 2) >> 1, h = (c - 2) & 1;
                           v = W_rel[r * 16384 + (h * 64 + j) * 128 + n]; }
        else             { if (j < 48) v = We_rel[(j >> 4) * 2048 + (j & 15) * 128 + n]; }
        __nv_bfloat16 hb = __float2bfloat16_rn(v);
        g_Wh[gtid] = hb;
        g_Wl[gtid] = __float2bfloat16_rn(v - __bfloat162float(hb));
    }

    const size_t nA = (size_t)N_REL * N_NODES * D_NODE / 4;
    const size_t nE = (size_t)N_NODES * 64 / 4;
    float4 z = make_float4(0.f, 0.f, 0.f, 0.f);
    float4* A4 = reinterpret_cast<float4*>(g_A);
    float4* E4 = reinterpret_cast<float4*>(g_E2);
    size_t stride = (size_t)gridDim.x * blockDim.x;
    for (size_t i = gtid; i < nA; i += stride) A4[i] = z;
    for (size_t i = gtid; i < nE; i += stride) E4[i] = z;
}

// ───────────── scatter: g_A[r][dst] += x[src]; g_E2[dst][r*16..] += attr ─────
__global__ void scatter_kernel(const float* __restrict__ x,
                               const float* __restrict__ edge_attr,
                               const int*   __restrict__ edge_index) {
    int w = (blockIdx.x * blockDim.x + threadIdx.x) >> 5;
    int lane = threadIdx.x & 31;
    if (w >= N_REL * N_EDGES) return;
    int r = w / N_EDGES;
    int e = w - r * N_EDGES;

    int2 se = reinterpret_cast<const int2*>(edge_index)[w];
    int src = se.x, dst = se.y;

    const float4* xr = reinterpret_cast<const float4*>(x + (size_t)src * D_NODE);
    float4 v = xr[lane];
    float* a = g_A + ((size_t)r * N_NODES + dst) * D_NODE + lane * 4;
    asm volatile("red.global.add.v4.f32 [%0], {%1,%2,%3,%4};"
                 :: "l"(a), "f"(v.x), "f"(v.y), "f"(v.z), "f"(v.w) : "memory");

    if (lane < 4) {
        const float4* er = reinterpret_cast<const float4*>(
            edge_attr + ((size_t)r * N_EDGES + e) * D_EDGE);
        float4 u = er[lane];
        float* ep = g_E2 + (size_t)dst * 64 + r * 16 + lane * 4;
        asm volatile("red.global.add.v4.f32 [%0], {%1,%2,%3,%4};"
                     :: "l"(ep), "f"(u.x), "f"(u.y), "f"(u.z), "f"(u.w) : "memory");
    }
}

// ───────────────── bf16x3 GEMM, full double-buffer + swizzle ──────────────────
__device__ __forceinline__ uint32_t smem_u32(const void* p) {
    uint32_t a;
    asm("{ .reg .u64 t; cvta.to.shared.u64 t, %1; cvt.u32.u64 %0, t; }" : "=r"(a) : "l"(p));
    return a;
}
__device__ __forceinline__ void ldsm4(uint32_t* r, uint32_t addr) {
    asm volatile("ldmatrix.sync.aligned.m8n8.x4.shared.b16 {%0,%1,%2,%3}, [%4];"
                 : "=r"(r[0]), "=r"(r[1]), "=r"(r[2]), "=r"(r[3]) : "r"(addr));
}
__device__ __forceinline__ void cpa16(uint32_t s, const void* g) {
    asm volatile("cp.async.ca.shared.global [%0], [%1], 16;" :: "r"(s), "l"(g));
}
__device__ __forceinline__ void mma16816(float* c, const uint32_t* a,
                                         uint32_t b0, uint32_t b1) {
    asm volatile(
        "mma.sync.aligned.m16n8k16.row.col.f32.bf16.bf16.f32 "
        "{%0,%1,%2,%3}, {%4,%5,%6,%7}, {%8,%9}, {%0,%1,%2,%3};"
        : "+f"(c[0]), "+f"(c[1]), "+f"(c[2]), "+f"(c[3])
        : "r"(a[0]), "r"(a[1]), "r"(a[2]), "r"(a[3]), "r"(b0), "r"(b1));
}
__device__ __forceinline__ void split8(const float* f, uint4& hi, uint4& lo) {
    uint32_t h[8], l[8];
#pragma unroll
    for (int j = 0; j < 8; ++j) {
        __nv_bfloat16 hb = __float2bfloat16_rn(f[j]);
        float r = f[j] - __bfloat162float(hb);
        __nv_bfloat16 lb = __float2bfloat16_rn(r);
        h[j] = (uint32_t)__bfloat16_as_ushort(hb);
        l[j] = (uint32_t)__bfloat16_as_ushort(lb);
    }
    hi.x = h[0] | (h[1] << 16); hi.y = h[2] | (h[3] << 16);
    hi.z = h[4] | (h[5] << 16); hi.w = h[6] | (h[7] << 16);
    lo.x = l[0] | (l[1] << 16); lo.y = l[2] | (l[3] << 16);
    lo.z = l[4] | (l[5] << 16); lo.w = l[6] | (l[7] << 16);
}

// smem stages: per stage [AH 16K | AL 16K | BH 16K | BL 16K] = 64 KB; ×2 stages
static constexpr int STAGE    = 65536;
static constexpr int OFF_AH   = 0;
static constexpr int OFF_AL   = 16384;
static constexpr int OFF_BH   = 32768;
static constexpr int OFF_BL   = 49152;
static constexpr int SMEM_TOTAL = 2 * STAGE;   // 131072

static constexpr int NC = 9;

struct Chunk { const float* a; int ld, kb; };

__device__ __forceinline__ Chunk chunk_desc(int c, const float* x) {
    Chunk d;
    if (c < 2)      { d.a = x; d.ld = 128; d.kb = c * 64; }
    else if (c < 8) { int r = (c - 2) >> 1, h = (c - 2) & 1;
                      d.a = g_A + (size_t)r * N_NODES * 128; d.ld = 128; d.kb = h * 64; }
    else            { d.a = g_E2; d.ld = 64; d.kb = 0; }
    return d;
}

__global__ __launch_bounds__(256, 1) void gemm_mma_kernel(
    const float* __restrict__ x,
    const float* __restrict__ bias,
    float* __restrict__ out) {
    extern __shared__ char smem[];
    uint32_t sbase = smem_u32(smem);

    int t = threadIdx.x;
    int wid = t >> 5, lane = t & 31;
    int wm = wid & 3, wn = wid >> 2;
    int m0 = blockIdx.x * 128;

    uint32_t xorv = (uint32_t)(lane & 7) << 4;

    // A ldmatrix: rows wm*32 + arow (+16 for mt=1), col-16B-sel by lane&16
    int arow = (lane & 7) + ((lane & 8) ? 8 : 0);
    uint32_t acb = (lane & 16) ? 16 : 0;
    uint32_t aRowByte0 = (uint32_t)(wm * 32 + arow) * 128;
    // B ldmatrix: rows wn*64 + brow + p*16, col-16B-sel by lane&8
    int brow = (lane & 7) + ((lane & 16) ? 8 : 0);
    uint32_t bcb = (lane & 8) ? 16 : 0;
    uint32_t bRowByte0 = (uint32_t)(wn * 64 + brow) * 128;

    int aRow = t >> 1, aHalf = t & 1;
    uint32_t aStoreRow = (uint32_t)aRow * 128;
    uint32_t aStoreXor = (uint32_t)(aRow & 7) << 4;
    float4 ar[8];

    auto load_a = [&](int c) {
        Chunk d = chunk_desc(c, x);
        int gr = m0 + aRow;
        const float* ap = d.a + (size_t)gr * d.ld + d.kb + aHalf * 32;
        if (gr < N_NODES) {
#pragma unroll
            for (int q = 0; q < 8; ++q)
                ar[q] = *reinterpret_cast<const float4*>(ap + q * 4);
        } else {
#pragma unroll
            for (int q = 0; q < 8; ++q) ar[q] = make_float4(0.f, 0.f, 0.f, 0.f);
        }
    };
    auto store_a = [&](int stage) {
        char* base = smem + stage * STAGE;
#pragma unroll
        for (int g = 0; g < 4; ++g) {
            float f[8];
            f[0]=ar[g*2].x; f[1]=ar[g*2].y; f[2]=ar[g*2].z; f[3]=ar[g*2].w;
            f[4]=ar[g*2+1].x; f[5]=ar[g*2+1].y; f[6]=ar[g*2+1].z; f[7]=ar[g*2+1].w;
            uint4 hi, lo; split8(f, hi, lo);
            uint32_t cbyte = (uint32_t)(64 * aHalf + 16 * g);
            uint32_t off = aStoreRow + (cbyte ^ aStoreXor);
            *reinterpret_cast<uint4*>(base + OFF_AH + off) = hi;
            *reinterpret_cast<uint4*>(base + OFF_AL + off) = lo;
        }
    };
    auto issue_b = [&](int c, int stage) {
        uint32_t bb = sbase + stage * STAGE;
        const __nv_bfloat16* gh = g_Wh + c * 8192;
        const __nv_bfloat16* gl = g_Wl + c * 8192;
#pragma unroll
        for (int i = 0; i < 4; ++i) {
            int task = t + i * 256;           // 1024 granules: n = task>>3, s16 = task&7
            int n = task >> 3, s16 = task & 7;
            uint32_t off = (uint32_t)n * 128 + (((uint32_t)s16 * 16) ^ ((uint32_t)(n & 7) << 4));
            cpa16(bb + OFF_BH + off, gh + n * 64 + s16 * 8);
            cpa16(bb + OFF_BL + off, gl + n * 64 + s16 * 8);
        }
    };

    float acc[2][8][4];
#pragma unroll
    for (int i = 0; i < 2; ++i)
#pragma unroll
        for (int j = 0; j < 8; ++j)
#pragma unroll
            for (int q = 0; q < 4; ++q) acc[i][j][q] = 0.f;

    // ── prologue: stage chunk 0 + prefetch chunk 1's A/B
    load_a(0);
    issue_b(0, 0);
    asm volatile("cp.async.commit_group;" ::: "memory");
    store_a(0);
    load_a(1);
    issue_b(1, 1);
    asm volatile("cp.async.commit_group;" ::: "memory");
    asm volatile("cp.async.wait_group 1;" ::: "memory");   // b(0) landed
    __syncthreads();

    for (int c = 0; c < NC; ++c) {
        int stage = c & 1;
        if (c + 1 < NC) store_a(stage ^ 1);                 // A(c+1) -> alt buffer
        if (c + 2 < NC) load_a(c + 2);                      // LDG hidden under MMA

        // ── MMA chunk c
        uint32_t sb = sbase + stage * STAGE;
#pragma unroll
        for (int ks = 0; ks < 4; ++ks) {
            uint32_t k0b = (uint32_t)ks * 32;
            uint32_t aCol = (k0b + acb) ^ xorv;
            uint32_t bCol = (k0b + bcb) ^ xorv;
            uint32_t ah[2][4], bh[4][4];
            ldsm4(ah[0], sb + OFF_AH + aRowByte0 + aCol);
            ldsm4(ah[1], sb + OFF_AH + aRowByte0 + 16 * 128 + aCol);
#pragma unroll
            for (int p = 0; p < 4; ++p)
                ldsm4(bh[p], sb + OFF_BH + bRowByte0 + p * 16 * 128 + bCol);
#pragma unroll
            for (int mt = 0; mt < 2; ++mt)
#pragma unroll
                for (int nt = 0; nt < 8; ++nt)
                    mma16816(acc[mt][nt], ah[mt],
                             bh[nt >> 1][(nt & 1) * 2], bh[nt >> 1][(nt & 1) * 2 + 1]);

            uint32_t al[2][4];
            ldsm4(al[0], sb + OFF_AL + aRowByte0 + aCol);
            ldsm4(al[1], sb + OFF_AL + aRowByte0 + 16 * 128 + aCol);
#pragma unroll
            for (int mt = 0; mt < 2; ++mt)
#pragma unroll
                for (int nt = 0; nt < 8; ++nt)
                    mma16816(acc[mt][nt], al[mt],
                             bh[nt >> 1][(nt & 1) * 2], bh[nt >> 1][(nt & 1) * 2 + 1]);

            uint32_t bl[4][4];
#pragma unroll
            for (int p = 0; p < 4; ++p)
                ldsm4(bl[p], sb + OFF_BL + bRowByte0 + p * 16 * 128 + bCol);
#pragma unroll
            for (int mt = 0; mt < 2; ++mt)
#pragma unroll
                for (int nt = 0; nt < 8; ++nt)
                    mma16816(acc[mt][nt], ah[mt],
                             bl[nt >> 1][(nt & 1) * 2], bl[nt >> 1][(nt & 1) * 2 + 1]);
        }
        __syncthreads();                                    // MMA(c) readers done; A(c+1) stored
        if (c + 2 < NC) {
            issue_b(c + 2, stage);                          // reuse freed B buffer
            asm volatile("cp.async.commit_group;" ::: "memory");
            asm volatile("cp.async.wait_group 1;" ::: "memory");   // b(c+1) landed
        } else {
            asm volatile("cp.async.wait_group 0;" ::: "memory");
        }
        __syncthreads();                                    // b(c+1) visible to all
    }

    // ── epilogue: + bias, relu, store
    int lr = lane >> 2, lc = lane & 3;
#pragma unroll
    for (int mt = 0; mt < 2; ++mt) {
        int r0 = m0 + wm * 32 + mt * 16 + lr;
        int r1 = r0 + 8;
#pragma unroll
        for (int nt = 0; nt < 8; ++nt) {
            int col = wn * 64 + nt * 8 + lc * 2;
            float b0 = bias[col], b1 = bias[col + 1];
            if (r0 < N_NODES) {
                float2 v;
                v.x = fmaxf(acc[mt][nt][0] + b0, 0.f);
                v.y = fmaxf(acc[mt][nt][1] + b1, 0.f);
                *reinterpret_cast<float2*>(out + (size_t)r0 * 128 + col) = v;
            }
            if (r1 < N_NODES) {
                float2 v;
                v.x = fmaxf(acc[mt][nt][2] + b0, 0.f);
                v.y = fmaxf(acc[mt][nt][3] + b1, 0.f);
                *reinterpret_cast<float2*>(out + (size_t)r1 * 128 + col) = v;
            }
        }
    }
}

// ───────────────────────── launch ─────────────────────────
extern "C" void kernel_launch(void* const* d_in, const int* in_sizes, int n_in,
                              void* d_out, int out_size) {
    const float* x          = (const float*)d_in[0];
    const float* edge_attr  = (const float*)d_in[1];
    const float* W_rel      = (const float*)d_in[2];
    const float* We_rel     = (const float*)d_in[3];
    const float* W_self     = (const float*)d_in[4];
    const float* b          = (const float*)d_in[5];
    const int*   edge_index = (const int*)d_in[6];
    float* out = (float*)d_out;

    static bool attr_set = false;
    if (!attr_set) {
        cudaFuncSetAttribute(gemm_mma_kernel,
                             cudaFuncAttributeMaxDynamicSharedMemorySize, SMEM_TOTAL);
        attr_set = true;
    }

    prep_kernel<<<2048, 256>>>(W_rel, We_rel, W_self);

    int n_warps = N_REL * N_EDGES;
    int blocks = (n_warps * 32 + 255) / 256;
    scatter_kernel<<<blocks, 256>>>(x, edge_attr, edge_index);

    int gblocks = (N_NODES + 127) / 128;  // 782
    gemm_mma_kernel<<<gblocks, 256, SMEM_TOTAL>>>(x, b, out);
}